// round 2
// baseline (speedup 1.0000x reference)
#include <cuda_runtime.h>

// score[i] = sigmoid(logits[u[i] * V + v[i]])
// u, v : int32 [B]; logits : fp32 [V*V]; out : fp32 [B]
__global__ void topos_gather_sigmoid(const int* __restrict__ u,
                                     const int* __restrict__ v,
                                     const float* __restrict__ logits,
                                     float* __restrict__ out,
                                     int B, int V) {
    int i = blockIdx.x * blockDim.x + threadIdx.x;
    if (i >= B) return;
    int ui = u[i];
    int vi = v[i];
    float x = __ldg(&logits[(long long)ui * V + vi]);
    out[i] = 1.0f / (1.0f + __expf(-x));
}

extern "C" void kernel_launch(void* const* d_in, const int* in_sizes, int n_in,
                              void* d_out, int out_size) {
    const int* u = (const int*)d_in[0];
    const int* v = (const int*)d_in[1];
    const float* logits = (const float*)d_in[2];
    float* out = (float*)d_out;

    const int B = in_sizes[0];      // 16384
    const int V = 8192;             // in_sizes[2] == V*V

    const int threads = 256;
    const int blocks = (B + threads - 1) / threads;
    topos_gather_sigmoid<<<blocks, threads>>>(u, v, logits, out, B, V);
}

// round 3
// speedup vs baseline: 1.0483x; 1.0483x over previous
#include <cuda_runtime.h>

// score[i] = sigmoid(logits[u[i] * V + v[i]])
// u, v : int32 [B]; logits : fp32 [V*V]; out : fp32 [B]
// Latency-bound gather: spread 16384 threads over all 148 SMs (256 blocks x 64
// threads) so per-SM L1tex wavefront queues stay shallow; both index loads
// issue before the dependent gather.
__global__ void __launch_bounds__(64, 32)
topos_gather_sigmoid(const int* __restrict__ u,
                     const int* __restrict__ v,
                     const float* __restrict__ logits,
                     float* __restrict__ out,
                     int B) {
    const int V_SHIFT = 13;  // V = 8192
    int i = blockIdx.x * 64 + threadIdx.x;
    if (i >= B) return;
    // Two independent index loads (MLP=2 on first round trip)
    int ui = __ldg(&u[i]);
    int vi = __ldg(&v[i]);
    float x = __ldg(&logits[((long long)ui << V_SHIFT) + vi]);
    out[i] = 1.0f / (1.0f + __expf(-x));
}

extern "C" void kernel_launch(void* const* d_in, const int* in_sizes, int n_in,
                              void* d_out, int out_size) {
    const int* u = (const int*)d_in[0];
    const int* v = (const int*)d_in[1];
    const float* logits = (const float*)d_in[2];
    float* out = (float*)d_out;

    const int B = in_sizes[0];  // 16384
    const int threads = 64;
    const int blocks = (B + threads - 1) / threads;  // 256
    topos_gather_sigmoid<<<blocks, threads>>>(u, v, logits, out, B);
}